// round 14
// baseline (speedup 1.0000x reference)
#include <cuda_runtime.h>
#include <cuda_fp16.h>

// ScaledDotProductAttention: B=4, H=1, S=4096, D=16, fp32.
// out = [context (B*S*D) | attn (B*S*S)]
// scores = QK^T/4 + (w*link + b); masked(true) -> -1e9; softmax; context = attn @ V.
// R13 structure (TQ=4, NT=128, 3 CTAs/SM, fp16 e buffer, predicated EX2, FFMA2)
// with K/V scratch as fp32 PLANE-SPLIT layout: plane j holds 16B chunk j of
// every row contiguously -> 4-line wavefronts per LDG.128 (same as fp16 rows)
// with ZERO h2->f2 conversion instructions and full fp32 K/V precision.

#define BATCH 4
#define SEQ   4096
#define DIM   16
#define TQ    4            // q-rows per CTA
#define NT    128          // threads per CTA
#define NWARP (NT / 32)

#define SMEM_BYTES (TQ * SEQ * 2)   // 32768 B fp16 e buffer

typedef unsigned long long u64;

// Plane-split fp32 scratch: Kpl[(b*4+j)*SEQ + row] = rows' j-th float4 chunk.
__device__ __align__(16) float4 Kpl[BATCH * 4 * SEQ];
__device__ __align__(16) float4 Vpl[BATCH * 4 * SEQ];

__device__ __forceinline__ u64 pk2(float lo, float hi) {
    u64 r; asm("mov.b64 %0, {%1, %2};" : "=l"(r) : "f"(lo), "f"(hi)); return r;
}
__device__ __forceinline__ void upk2(u64 v, float& lo, float& hi) {
    asm("mov.b64 {%0, %1}, %2;" : "=f"(lo), "=f"(hi) : "l"(v));
}
__device__ __forceinline__ u64 fma2(u64 a, u64 b, u64 c) {
    u64 d; asm("fma.rn.f32x2 %0, %1, %2, %3;" : "=l"(d) : "l"(a), "l"(b), "l"(c)); return d;
}
__device__ __forceinline__ u64 mul2(u64 a, u64 b) {
    u64 d; asm("mul.rn.f32x2 %0, %1, %2;" : "=l"(d) : "l"(a), "l"(b)); return d;
}

// -------- prelude: reshuffle K/V into plane-split layout (2 MB, ~3 us) --------
__global__ void shuf_kv_kernel(const float4* __restrict__ K4,
                               const float4* __restrict__ V4)
{
    const int i = blockIdx.x * blockDim.x + threadIdx.x;   // 65536 = B*S*D/4 chunks
    const int row = i >> 2;            // global row 0..16383
    const int j   = i & 3;             // chunk within row
    const int b   = row >> 12;         // row / SEQ
    const int rl  = row & (SEQ - 1);   // row % SEQ
    Kpl[((b << 2) + j) * SEQ + rl] = K4[i];
    Vpl[((b << 2) + j) * SEQ + rl] = V4[i];
}

__global__ __launch_bounds__(NT, 3)
void sdpa_fused_kernel(const float* __restrict__ Qp,
                       const int*   __restrict__ Mp,
                       const float* __restrict__ Lp,
                       const float* __restrict__ swp,
                       const float* __restrict__ sbp,
                       float* __restrict__ ctx,
                       float* __restrict__ attn)
{
    extern __shared__ __half scr[];                // TQ*SEQ fp16 e values
    __shared__ float qs[TQ * DIM];
    __shared__ float redw[TQ * NWARP];
    __shared__ float sinv[TQ];
    __shared__ float redc[NWARP * TQ * DIM];       // context partials (1 KB)

    const int tid = threadIdx.x;
    const int wp  = tid >> 5;
    const int ln  = tid & 31;
    const int b   = blockIdx.x / (SEQ / TQ);
    const int q0  = (blockIdx.x % (SEQ / TQ)) * TQ;

    const float LOG2E = 1.44269504088896f;
    const float w2 = (*swp) * LOG2E;
    const float b2 = (*sbp) * LOG2E;
    const float S2 = 0.25f * LOG2E;                // (1/sqrt(16)) * log2e

    if (tid < TQ * DIM)
        qs[tid] = Qp[((size_t)b * SEQ + q0) * DIM + tid];
    __syncthreads();

    u64 q2[TQ * 8];
    #pragma unroll
    for (int q = 0; q < TQ; q++)
        #pragma unroll
        for (int i = 0; i < 8; i++)
            q2[q * 8 + i] = pk2(qs[q * DIM + 2 * i], qs[q * DIM + 2 * i + 1]);

    const float4* Kp0 = Kpl + (size_t)(b * 4 + 0) * SEQ;
    const float4* Kp1 = Kpl + (size_t)(b * 4 + 1) * SEQ;
    const float4* Kp2 = Kpl + (size_t)(b * 4 + 2) * SEQ;
    const float4* Kp3 = Kpl + (size_t)(b * 4 + 3) * SEQ;
    const float4* Vp0 = Vpl + (size_t)(b * 4 + 0) * SEQ;
    const float4* Vp1 = Vpl + (size_t)(b * 4 + 1) * SEQ;
    const float4* Vp2 = Vpl + (size_t)(b * 4 + 2) * SEQ;
    const float4* Vp3 = Vpl + (size_t)(b * 4 + 3) * SEQ;
    const float*  Lb  = Lp + (size_t)b * SEQ * SEQ;
    const int*    Mb  = Mp + (size_t)b * SEQ * SEQ;
    float* Ab = attn + (size_t)b * SEQ * SEQ;

    // ============ Phase A: e = ex2(score*log2e) -> fp16 smem; row sums ============
    float sloc[TQ];
    #pragma unroll
    for (int q = 0; q < TQ; q++) sloc[q] = 0.0f;

    #pragma unroll 2
    for (int k = tid; k < SEQ; k += NT) {
        float4 c0 = Kp0[k];
        float4 c1 = Kp1[k];
        float4 c2 = Kp2[k];
        float4 c3 = Kp3[k];
        u64 kk[8];
        kk[0] = pk2(c0.x, c0.y); kk[1] = pk2(c0.z, c0.w);
        kk[2] = pk2(c1.x, c1.y); kk[3] = pk2(c1.z, c1.w);
        kk[4] = pk2(c2.x, c2.y); kk[5] = pk2(c2.z, c2.w);
        kk[6] = pk2(c3.x, c3.y); kk[7] = pk2(c3.z, c3.w);

        float lk[TQ];
        int   mk[TQ];
        #pragma unroll
        for (int q = 0; q < TQ; q++) lk[q] = Lb[(size_t)(q0 + q) * SEQ + k];
        #pragma unroll
        for (int q = 0; q < TQ; q++) mk[q] = Mb[(size_t)(q0 + q) * SEQ + k];

        #pragma unroll
        for (int q = 0; q < TQ; q++) {
            const u64* qq = &q2[q * 8];
            u64 d2 = mul2(qq[0], kk[0]);
            d2 = fma2(qq[1], kk[1], d2);
            d2 = fma2(qq[2], kk[2], d2);
            d2 = fma2(qq[3], kk[3], d2);
            d2 = fma2(qq[4], kk[4], d2);
            d2 = fma2(qq[5], kk[5], d2);
            d2 = fma2(qq[6], kk[6], d2);
            d2 = fma2(qq[7], kk[7], d2);
            float dl, dh;
            upk2(d2, dl, dh);
            float dot = dl + dh;
            float sc2 = fmaf(w2, lk[q], b2);
            sc2 = fmaf(dot, S2, sc2);
            float e = 0.0f;
            if (!mk[q])
                asm("ex2.approx.ftz.f32 %0, %1;" : "=f"(e) : "f"(sc2));
            __half he = __float2half_rn(e);
            scr[q * SEQ + k] = he;
            sloc[q] += __half2float(he);       // sum the ROUNDED value
        }
    }

    // ---- reduce row sums ----
    #pragma unroll
    for (int q = 0; q < TQ; q++) {
        #pragma unroll
        for (int o = 16; o > 0; o >>= 1)
            sloc[q] += __shfl_xor_sync(0xffffffffu, sloc[q], o);
    }
    if (ln == 0) {
        #pragma unroll
        for (int q = 0; q < TQ; q++) redw[q * NWARP + wp] = sloc[q];
    }
    __syncthreads();
    if (tid < TQ) {
        float s = 0.0f;
        #pragma unroll
        for (int t = 0; t < NWARP; t++) s += redw[tid * NWARP + t];
        sinv[tid] = 1.0f / s;
    }
    __syncthreads();

    // ============ Phase E: attn = e * inv; context accumulate (packed) ============
    float inv[TQ];
    #pragma unroll
    for (int q = 0; q < TQ; q++) inv[q] = sinv[q];

    u64 acc2[TQ * 8];
    #pragma unroll
    for (int i = 0; i < TQ * 8; i++) acc2[i] = 0ull;

    #pragma unroll 2
    for (int k = tid; k < SEQ; k += NT) {
        float4 c0 = Vp0[k];
        float4 c1 = Vp1[k];
        float4 c2 = Vp2[k];
        float4 c3 = Vp3[k];
        u64 vv[8];
        vv[0] = pk2(c0.x, c0.y); vv[1] = pk2(c0.z, c0.w);
        vv[2] = pk2(c1.x, c1.y); vv[3] = pk2(c1.z, c1.w);
        vv[4] = pk2(c2.x, c2.y); vv[5] = pk2(c2.z, c2.w);
        vv[6] = pk2(c3.x, c3.y); vv[7] = pk2(c3.z, c3.w);

        #pragma unroll
        for (int q = 0; q < TQ; q++) {
            float a = __half2float(scr[q * SEQ + k]) * inv[q];
            Ab[(size_t)(q0 + q) * SEQ + k] = a;
            u64 aa = pk2(a, a);
            u64* A = &acc2[q * 8];
            A[0] = fma2(aa, vv[0], A[0]);
            A[1] = fma2(aa, vv[1], A[1]);
            A[2] = fma2(aa, vv[2], A[2]);
            A[3] = fma2(aa, vv[3], A[3]);
            A[4] = fma2(aa, vv[4], A[4]);
            A[5] = fma2(aa, vv[5], A[5]);
            A[6] = fma2(aa, vv[6], A[6]);
            A[7] = fma2(aa, vv[7], A[7]);
        }
    }

    // ---- unpack + multi-value warp butterfly: 64 sums -> lane ln owns {2ln, 2ln+1} ----
    float acc[TQ * DIM];
    #pragma unroll
    for (int i = 0; i < TQ * 8; i++)
        upk2(acc2[i], acc[2 * i], acc[2 * i + 1]);

    #pragma unroll
    for (int o = 16, n = 32; o >= 1; o >>= 1, n >>= 1) {
        const bool hi = (ln & o) != 0;
        #pragma unroll
        for (int i = 0; i < n; i++) {
            float s    = hi ? acc[i] : acc[i + n];
            float r    = __shfl_xor_sync(0xffffffffu, s, o);
            float mine = hi ? acc[i + n] : acc[i];
            acc[i] = mine + r;
        }
    }
    *(float2*)&redc[wp * (TQ * DIM) + 2 * ln] = make_float2(acc[0], acc[1]);
    __syncthreads();

    if (tid < TQ * DIM) {
        float s = 0.0f;
        #pragma unroll
        for (int ww = 0; ww < NWARP; ww++)
            s += redc[ww * (TQ * DIM) + tid];
        const int q = tid >> 4, d = tid & 15;
        ctx[((size_t)b * SEQ + q0 + q) * DIM + d] = s;
    }
}

extern "C" void kernel_launch(void* const* d_in, const int* in_sizes, int n_in,
                              void* d_out, int out_size)
{
    const float* Q  = (const float*)d_in[0];
    const float* K  = (const float*)d_in[1];
    const float* V  = (const float*)d_in[2];
    const int*   M  = (const int*)d_in[3];
    const float* L  = (const float*)d_in[4];
    const float* sw = (const float*)d_in[5];
    const float* sb = (const float*)d_in[6];

    float* ctx  = (float*)d_out;                               // B*S*D
    float* attn = (float*)d_out + (size_t)BATCH * SEQ * DIM;   // B*S*S

    // prelude: reshuffle K/V into plane-split fp32 layout (65536 chunks)
    shuf_kv_kernel<<<256, 256>>>((const float4*)K, (const float4*)V);

    cudaFuncSetAttribute(sdpa_fused_kernel,
                         cudaFuncAttributeMaxDynamicSharedMemorySize, SMEM_BYTES);

    dim3 grid(BATCH * (SEQ / TQ));
    sdpa_fused_kernel<<<grid, NT, SMEM_BYTES>>>(Q, M, L, sw, sb, ctx, attn);
}